// round 12
// baseline (speedup 1.0000x reference)
#include <cuda_runtime.h>
#include <cuda_bf16.h>
#include <math.h>

// Problem constants
#define BB 2
#define SS 2048
#define NTOK (BB*SS)            // 4096
#define HIDDEN 4096
#define H 32
#define HK 8
#define D 128
#define QKV_COLS ((H + 2*HK) * D)   // 6144
#define K_OFF (H*D)                 // 4096
#define V_OFF (H*D + HK*D)          // 5120
#define SCALE 0.08838834764831845f  // 1/sqrt(128)

// Scratch (static device globals — no runtime allocation)
__device__ float g_qkv[(size_t)NTOK * QKV_COLS];   // ~100 MB
__device__ float g_attn[(size_t)NTOK * (H*D)];     // ~67 MB
// RoPE cos/sin table
__device__ float g_cosT[SS * 64];
__device__ float g_sinT[SS * 64];
// pre-split bf16 operands for flash attention
__device__ __nv_bfloat16 g_qh[(size_t)BB*H*SS*D];     // [b,h,s,d] (row-major)
__device__ __nv_bfloat16 g_ql[(size_t)BB*H*SS*D];
// K packed fragment-major: per key row, 256 elems: (kc*4+tg)*8 + {hi k,k+1,k+8,k+9, lo ...}
__device__ __nv_bfloat16 g_kp[(size_t)BB*HK*SS*256];
// V packed fragment-major: per d row, per 64-key tile, 128 elems
__device__ __nv_bfloat16 g_vp[(size_t)BB*HK*D*(SS/64)*128];

__device__ __forceinline__ unsigned f2tf32(float x) {
    unsigned r;
    asm("cvt.rna.tf32.f32 %0, %1;" : "=r"(r) : "f"(x));
    return r;
}

// packed index within a 16-element k-chunk group (hi at +0..3, lo at +4..7)
__device__ __forceinline__ int pack_idx(int e) {
    const int kc = e >> 4, r = e & 15;
    const int tg = (r & 7) >> 1, half = r >> 3, eo = r & 1;
    return (kc*4 + tg)*8 + half*2 + eo;
}

// ---------------------------------------------------------------------------
// TF32 tensor-core GEMM (R2/R6-proven): C = A @ B row-major fp32.
// 128x128 block tile, BK=32, 256 threads (8 warps), warp tile 64x32.
// 126 regs -> exactly 2 CTAs/SM; do not perturb.
// ---------------------------------------------------------------------------
#define AS_STRIDE 36
#define BS_STRIDE 136

__global__ __launch_bounds__(256) void tf32_gemm_kernel(
    const float* __restrict__ A, const float* __restrict__ B,
    float* __restrict__ C, int M, int N, int K)
{
    __shared__ float As[128][AS_STRIDE];
    __shared__ float Bs[32][BS_STRIDE];

    const int tid  = threadIdx.x;
    const int wid  = tid >> 5;
    const int lane = tid & 31;
    const int g    = lane >> 2;
    const int tg   = lane & 3;

    const int wm = (wid & 1) * 64;
    const int wn = (wid >> 1) * 32;

    const int bm = blockIdx.y * 128;
    const int bn = blockIdx.x * 128;

    const int arow = tid >> 3;
    const int ac4  = tid & 7;
    const int brow = tid >> 5;
    const int bc4  = tid & 31;

    float acc[4][4][4];
#pragma unroll
    for (int i = 0; i < 4; i++)
#pragma unroll
        for (int j = 0; j < 4; j++)
#pragma unroll
            for (int c = 0; c < 4; c++) acc[i][j][c] = 0.f;

    for (int k0 = 0; k0 < K; k0 += 32) {
#pragma unroll
        for (int p = 0; p < 4; p++) {
            float4 v = *(const float4*)&A[(size_t)(bm + arow + 32*p) * K + k0 + ac4*4];
            v.x = __uint_as_float(f2tf32(v.x));
            v.y = __uint_as_float(f2tf32(v.y));
            v.z = __uint_as_float(f2tf32(v.z));
            v.w = __uint_as_float(f2tf32(v.w));
            *(float4*)&As[arow + 32*p][ac4*4] = v;
        }
#pragma unroll
        for (int p = 0; p < 4; p++) {
            float4 v = *(const float4*)&B[(size_t)(k0 + brow + 8*p) * N + bn + bc4*4];
            v.x = __uint_as_float(f2tf32(v.x));
            v.y = __uint_as_float(f2tf32(v.y));
            v.z = __uint_as_float(f2tf32(v.z));
            v.w = __uint_as_float(f2tf32(v.w));
            *(float4*)&Bs[brow + 8*p][bc4*4] = v;
        }
        __syncthreads();

#pragma unroll
        for (int ks = 0; ks < 4; ks++) {
            unsigned a[4][4], b[4][2];
#pragma unroll
            for (int i = 0; i < 4; i++) {
                const int r = wm + i*16 + g;
                a[i][0] = __float_as_uint(As[r    ][ks*8 + tg    ]);
                a[i][1] = __float_as_uint(As[r + 8][ks*8 + tg    ]);
                a[i][2] = __float_as_uint(As[r    ][ks*8 + tg + 4]);
                a[i][3] = __float_as_uint(As[r + 8][ks*8 + tg + 4]);
            }
#pragma unroll
            for (int j = 0; j < 4; j++) {
                const int c = wn + j*8 + g;
                b[j][0] = __float_as_uint(Bs[ks*8 + tg    ][c]);
                b[j][1] = __float_as_uint(Bs[ks*8 + tg + 4][c]);
            }
#pragma unroll
            for (int i = 0; i < 4; i++)
#pragma unroll
                for (int j = 0; j < 4; j++) {
                    asm volatile(
                        "mma.sync.aligned.m16n8k8.row.col.f32.tf32.tf32.f32 "
                        "{%0,%1,%2,%3}, {%4,%5,%6,%7}, {%8,%9}, {%0,%1,%2,%3};"
                        : "+f"(acc[i][j][0]), "+f"(acc[i][j][1]),
                          "+f"(acc[i][j][2]), "+f"(acc[i][j][3])
                        : "r"(a[i][0]), "r"(a[i][1]), "r"(a[i][2]), "r"(a[i][3]),
                          "r"(b[j][0]), "r"(b[j][1]));
                }
        }
        __syncthreads();
    }

#pragma unroll
    for (int i = 0; i < 4; i++)
#pragma unroll
        for (int j = 0; j < 4; j++) {
            const int row = bm + wm + i*16 + g;
            const int col = bn + wn + j*8 + tg*2;
            float2 v0 = make_float2(acc[i][j][0], acc[i][j][1]);
            float2 v1 = make_float2(acc[i][j][2], acc[i][j][3]);
            *(float2*)&C[(size_t)row       * N + col] = v0;
            *(float2*)&C[(size_t)(row + 8) * N + col] = v1;
        }
}

// ---------------------------------------------------------------------------
// RoPE table
// ---------------------------------------------------------------------------
__global__ __launch_bounds__(256) void rope_table_kernel(const int* __restrict__ positions)
{
    const int idx = blockIdx.x * 256 + threadIdx.x;
    if (idx >= SS * 64) return;
    const int d = idx & 63;
    const int s = idx >> 6;
    const float pos = (float)positions[s];
    const float inv = (float)pow(10000.0, -(double)(2 * d) / 128.0);
    float sn, cn;
    sincosf(pos * inv, &sn, &cn);
    g_cosT[idx] = cn;
    g_sinT[idx] = sn;
}

// ---------------------------------------------------------------------------
// prep_qk: RoPE (table) + (scale for q) + bf16 hi/lo split.
// Q -> head-major row layout; K -> packed fragment-major layout (g_kp).
// ---------------------------------------------------------------------------
__global__ __launch_bounds__(256) void prep_qk_kernel()
{
    const int idx = blockIdx.x * 256 + threadIdx.x;
    const int total = NTOK * 40 * 64;
    if (idx >= total) return;

    const int d  = idx & 63;
    const int h  = (idx >> 6) % 40;
    const int t  = idx / (64 * 40);
    const int b  = t / SS;
    const int s  = t & (SS - 1);

    const float cn = g_cosT[s * 64 + d];
    const float sn = g_sinT[s * 64 + d];

    float x1, x2;
    if (h < H) {
        const float* row = g_qkv + (size_t)t * QKV_COLS + h * D;
        x1 = row[d]; x2 = row[d + 64];
    } else {
        const float* row = g_qkv + (size_t)t * QKV_COLS + K_OFF + (h - H) * D;
        x1 = row[d]; x2 = row[d + 64];
    }
    float y1 = x1 * cn - x2 * sn;
    float y2 = x2 * cn + x1 * sn;

    if (h < H) {
        y1 *= SCALE; y2 *= SCALE;
        const size_t base = ((size_t)(b * H + h) * SS + s) * D;
        __nv_bfloat16 h1 = __float2bfloat16(y1), h2 = __float2bfloat16(y2);
        g_qh[base + d]      = h1;
        g_qh[base + d + 64] = h2;
        g_ql[base + d]      = __float2bfloat16(y1 - __bfloat162float(h1));
        g_ql[base + d + 64] = __float2bfloat16(y2 - __bfloat162float(h2));
    } else {
        const size_t base = ((size_t)(b * HK + (h - H)) * SS + s) * 256;
        __nv_bfloat16 h1 = __float2bfloat16(y1), h2 = __float2bfloat16(y2);
        __nv_bfloat16 l1 = __float2bfloat16(y1 - __bfloat162float(h1));
        __nv_bfloat16 l2 = __float2bfloat16(y2 - __bfloat162float(h2));
        const int p1 = pack_idx(d);
        const int p2 = pack_idx(d + 64);
        g_kp[base + p1]     = h1;
        g_kp[base + p1 + 4] = l1;
        g_kp[base + p2]     = h2;
        g_kp[base + p2 + 4] = l2;
    }
}

// ---------------------------------------------------------------------------
// prep_v: transpose V to [bk][d][kt-tile packed 128] with bf16 hi/lo split
// ---------------------------------------------------------------------------
__global__ void prep_v_kernel()
{
    __shared__ float tile[32][33];

    const int s0 = blockIdx.x * 32;
    const int d0 = blockIdx.y * 32;
    const int bk = blockIdx.z;
    const int b  = bk / HK;
    const int kvh = bk % HK;

    const int tx = threadIdx.x;
    const int ty = threadIdx.y;

#pragma unroll
    for (int j = 0; j < 4; j++) {
        const int s = s0 + ty + 8*j;
        tile[ty + 8*j][tx] =
            g_qkv[(size_t)(b*SS + s) * QKV_COLS + V_OFF + kvh*D + d0 + tx];
    }
    __syncthreads();

    const int s  = s0 + tx;
    const int st = s >> 6;          // 64-key tile index
    const int sl = s & 63;          // local key in tile
    // packed key index within tile (kc in 0..3)
    const int kc = sl >> 4, r = sl & 15;
    const int tg = (r & 7) >> 1, half = r >> 3, eo = r & 1;
    const int p  = (kc*4 + tg)*8 + half*2 + eo;

#pragma unroll
    for (int j = 0; j < 4; j++) {
        const int d = d0 + ty + 8*j;
        const float x = tile[tx][ty + 8*j];
        const size_t o = (((size_t)(b*HK + kvh) * D + d) * (SS/64) + st) * 128 + p;
        __nv_bfloat16 hx = __float2bfloat16(x);
        g_vp[o]     = hx;
        g_vp[o + 4] = __float2bfloat16(x - __bfloat162float(hx));
    }
}

// ---------------------------------------------------------------------------
// Tensor-core flash attention: Q fragments register-hoisted (R11-proven),
// K/V in packed fragment-major layout -> one LDS.128 per fragment quad.
// XOR swizzle ((row&1)<<2 on the uint4 index) kills bank conflicts.
// 128 threads (4 warps), __launch_bounds__(128,2) pins 2 CTAs/SM.
// smem: Q 2x64x136 + K 64x256 + V 128x128 bf16 = 100,352 B.
// ---------------------------------------------------------------------------
#define QSTR 136
#define FLASH2_SMEM ((2*64*QSTR + 64*256 + 128*128) * sizeof(__nv_bfloat16))

__device__ __forceinline__ void mma_bf16(float* c, unsigned a0, unsigned a1,
                                         unsigned a2, unsigned a3,
                                         unsigned b0, unsigned b1)
{
    asm volatile(
        "mma.sync.aligned.m16n8k16.row.col.f32.bf16.bf16.f32 "
        "{%0,%1,%2,%3}, {%4,%5,%6,%7}, {%8,%9}, {%0,%1,%2,%3};"
        : "+f"(c[0]), "+f"(c[1]), "+f"(c[2]), "+f"(c[3])
        : "r"(a0), "r"(a1), "r"(a2), "r"(a3), "r"(b0), "r"(b1));
}

__device__ __forceinline__ unsigned pack2bf(float x, float y) {
    __nv_bfloat162 t = __floats2bfloat162_rn(x, y);
    return *(unsigned*)&t;
}

__global__ __launch_bounds__(128, 2) void flash_tc_kernel()
{
    const int qt = blockIdx.x;
    const int h  = blockIdx.y;
    const int b  = blockIdx.z;
    const int kvh = h >> 2;

    extern __shared__ __nv_bfloat16 sm2[];
    __nv_bfloat16* Qhi = sm2;
    __nv_bfloat16* Qlo = Qhi + 64*QSTR;
    __nv_bfloat16* Ks  = Qlo + 64*QSTR;      // packed, 64 rows x 256
    __nv_bfloat16* Vp  = Ks + 64*256;        // packed, 128 rows x 128

    const int tid  = threadIdx.x;
    const int warp = tid >> 5;
    const int lane = tid & 31;
    const int g    = lane >> 2;
    const int tg   = lane & 3;

    // ---- stage Q (pure uint4 copies) ----
    {
        const __nv_bfloat16* srcs[2] = {
            g_qh + ((size_t)(b*H + h) * SS + qt*64) * D,
            g_ql + ((size_t)(b*H + h) * SS + qt*64) * D };
        __nv_bfloat16* dsts[2] = { Qhi, Qlo };
#pragma unroll
        for (int a = 0; a < 2; a++)
            for (int i = tid; i < 64*16; i += 128) {
                const int row = i >> 4, c8 = i & 15;
                *(uint4*)&dsts[a][row*QSTR + c8*8] =
                    *(const uint4*)&srcs[a][(size_t)row*D + c8*8];
            }
    }
    __syncthreads();

    const int row0 = warp*16 + g;
    const int gsw  = (g & 1) << 2;   // XOR swizzle term for fragment reads

    // ---- hoist Q fragments to registers (loop-invariant across kt) ----
    unsigned qf[8][8];
#pragma unroll
    for (int kc = 0; kc < 8; kc++) {
        const int ko = kc*16 + tg*2;
        qf[kc][0] = *(unsigned*)&Qhi[(row0    )*QSTR + ko];
        qf[kc][1] = *(unsigned*)&Qhi[(row0 + 8)*QSTR + ko];
        qf[kc][2] = *(unsigned*)&Qhi[(row0    )*QSTR + ko + 8];
        qf[kc][3] = *(unsigned*)&Qhi[(row0 + 8)*QSTR + ko + 8];
        qf[kc][4] = *(unsigned*)&Qlo[(row0    )*QSTR + ko];
        qf[kc][5] = *(unsigned*)&Qlo[(row0 + 8)*QSTR + ko];
        qf[kc][6] = *(unsigned*)&Qlo[(row0    )*QSTR + ko + 8];
        qf[kc][7] = *(unsigned*)&Qlo[(row0 + 8)*QSTR + ko + 8];
    }

    float m0 = -1e30f, m1 = -1e30f, l0 = 0.f, l1 = 0.f;
    float oAcc[16][4];
#pragma unroll
    for (int dt = 0; dt < 16; dt++)
#pragma unroll
        for (int c = 0; c < 4; c++) oAcc[dt][c] = 0.f;

    const __nv_bfloat16* kp_base = g_kp + (size_t)(b*HK + kvh) * SS * 256;
    const __nv_bfloat16* vp_base = g_vp + (size_t)(b*HK + kvh) * D * (SS/64) * 128;

    for (int kt = 0; kt <= qt; kt++) {
        __syncthreads();   // protect K/V smem from previous iteration's readers
        // ---- stage K (packed rows, swizzled smem slots) ----
        for (int i = tid; i < 64*32; i += 128) {
            const int r = i >> 5, c = i & 31;
            const int cs = c ^ ((r & 1) << 2);
            *(uint4*)&Ks[r*256 + cs*8] =
                *(const uint4*)&kp_base[(size_t)(kt*64 + r)*256 + c*8];
        }
        // ---- stage V (packed tiles, swizzled) ----
        for (int i = tid; i < 128*16; i += 128) {
            const int dd = i >> 4, c = i & 15;
            const int cs = c ^ ((dd & 1) << 2);
            *(uint4*)&Vp[dd*128 + cs*8] =
                *(const uint4*)&vp_base[((size_t)dd*(SS/64) + kt)*128 + c*8];
        }
        __syncthreads();

        // ---- S = Q @ K^T (one LDS.128 per fragment quad) ----
        float sAcc[8][4];
#pragma unroll
        for (int nt = 0; nt < 8; nt++)
#pragma unroll
            for (int c = 0; c < 4; c++) sAcc[nt][c] = 0.f;

#pragma unroll
        for (int kc = 0; kc < 8; kc++) {
            const int idx = (kc*4 + tg) ^ gsw;
#pragma unroll
            for (int nt = 0; nt < 8; nt++) {
                const uint4 f = *(const uint4*)&Ks[(nt*8 + g)*256 + idx*8];
                mma_bf16(sAcc[nt], qf[kc][0], qf[kc][1], qf[kc][2], qf[kc][3], f.x, f.y);
                mma_bf16(sAcc[nt], qf[kc][0], qf[kc][1], qf[kc][2], qf[kc][3], f.z, f.w);
                mma_bf16(sAcc[nt], qf[kc][4], qf[kc][5], qf[kc][6], qf[kc][7], f.x, f.y);
            }
        }

        if (kt == qt) {
#pragma unroll
            for (int nt = 0; nt < 8; nt++) {
                const int col = nt*8 + tg*2;
                if (col     > row0    ) sAcc[nt][0] = -1e30f;
                if (col + 1 > row0    ) sAcc[nt][1] = -1e30f;
                if (col     > row0 + 8) sAcc[nt][2] = -1e30f;
                if (col + 1 > row0 + 8) sAcc[nt][3] = -1e30f;
            }
        }

        float mt0 = -1e30f, mt1 = -1e30f;
#pragma unroll
        for (int nt = 0; nt < 8; nt++) {
            mt0 = fmaxf(mt0, fmaxf(sAcc[nt][0], sAcc[nt][1]));
            mt1 = fmaxf(mt1, fmaxf(sAcc[nt][2], sAcc[nt][3]));
        }
        mt0 = fmaxf(mt0, __shfl_xor_sync(0xffffffffu, mt0, 1));
        mt0 = fmaxf(mt0, __shfl_xor_sync(0xffffffffu, mt0, 2));
        mt1 = fmaxf(mt1, __shfl_xor_sync(0xffffffffu, mt1, 1));
        mt1 = fmaxf(mt1, __shfl_xor_sync(0xffffffffu, mt1, 2));

        const float mn0 = fmaxf(m0, mt0);
        const float mn1 = fmaxf(m1, mt1);
        const float cr0 = __expf(m0 - mn0);
        const float cr1 = __expf(m1 - mn1);

        float sum0 = 0.f, sum1 = 0.f;
#pragma unroll
        for (int nt = 0; nt < 8; nt++) {
            sAcc[nt][0] = __expf(sAcc[nt][0] - mn0);
            sAcc[nt][1] = __expf(sAcc[nt][1] - mn0);
            sAcc[nt][2] = __expf(sAcc[nt][2] - mn1);
            sAcc[nt][3] = __expf(sAcc[nt][3] - mn1);
            sum0 += sAcc[nt][0] + sAcc[nt][1];
            sum1 += sAcc[nt][2] + sAcc[nt][3];
        }
        l0 = l0 * cr0 + sum0;
        l1 = l1 * cr1 + sum1;
        m0 = mn0; m1 = mn1;

#pragma unroll
        for (int dt = 0; dt < 16; dt++) {
            oAcc[dt][0] *= cr0; oAcc[dt][1] *= cr0;
            oAcc[dt][2] *= cr1; oAcc[dt][3] *= cr1;
        }

        // ---- O += P @ V (one LDS.128 per fragment quad) ----
#pragma unroll
        for (int kc = 0; kc < 4; kc++) {
            float p00 = sAcc[2*kc][0],   p01 = sAcc[2*kc][1];
            float p02 = sAcc[2*kc][2],   p03 = sAcc[2*kc][3];
            float p10 = sAcc[2*kc+1][0], p11 = sAcc[2*kc+1][1];
            float p12 = sAcc[2*kc+1][2], p13 = sAcc[2*kc+1][3];

            __nv_bfloat16 h00=__float2bfloat16(p00), h01=__float2bfloat16(p01);
            __nv_bfloat16 h02=__float2bfloat16(p02), h03=__float2bfloat16(p03);
            __nv_bfloat16 h10=__float2bfloat16(p10), h11=__float2bfloat16(p11);
            __nv_bfloat16 h12=__float2bfloat16(p12), h13=__float2bfloat16(p13);

            __nv_bfloat162 t0(h00,h01), t1(h02,h03), t2(h10,h11), t3(h12,h13);
            unsigned ah0 = *(unsigned*)&t0;
            unsigned ah1 = *(unsigned*)&t1;
            unsigned ah2 = *(unsigned*)&t2;
            unsigned ah3 = *(unsigned*)&t3;

            unsigned al0 = pack2bf(p00 - __bfloat162float(h00), p01 - __bfloat162float(h01));
            unsigned al1 = pack2bf(p02 - __bfloat162float(h02), p03 - __bfloat162float(h03));
            unsigned al2 = pack2bf(p10 - __bfloat162float(h10), p11 - __bfloat162float(h11));
            unsigned al3 = pack2bf(p12 - __bfloat162float(h12), p13 - __bfloat162float(h13));

            const int idx = (kc*4 + tg) ^ gsw;
#pragma unroll
            for (int dt = 0; dt < 16; dt++) {
                const uint4 f = *(const uint4*)&Vp[(dt*8 + g)*128 + idx*8];
                mma_bf16(oAcc[dt], ah0, ah1, ah2, ah3, f.x, f.y);
                mma_bf16(oAcc[dt], ah0, ah1, ah2, ah3, f.z, f.w);
                mma_bf16(oAcc[dt], al0, al1, al2, al3, f.x, f.y);
            }
        }
    }

    l0 += __shfl_xor_sync(0xffffffffu, l0, 1);
    l0 += __shfl_xor_sync(0xffffffffu, l0, 2);
    l1 += __shfl_xor_sync(0xffffffffu, l1, 1);
    l1 += __shfl_xor_sync(0xffffffffu, l1, 2);
    const float inv0 = 1.f / l0;
    const float inv1 = 1.f / l1;

    const int tok0 = b*SS + qt*64 + row0;
#pragma unroll
    for (int dt = 0; dt < 16; dt++) {
        const int col = h*D + dt*8 + tg*2;
        float2 v0 = make_float2(oAcc[dt][0]*inv0, oAcc[dt][1]*inv0);
        float2 v1 = make_float2(oAcc[dt][2]*inv1, oAcc[dt][3]*inv1);
        *(float2*)&g_attn[(size_t)tok0       * (H*D) + col] = v0;
        *(float2*)&g_attn[(size_t)(tok0 + 8) * (H*D) + col] = v1;
    }
}

// ---------------------------------------------------------------------------
// launch
// ---------------------------------------------------------------------------
extern "C" void kernel_launch(void* const* d_in, const int* in_sizes, int n_in,
                              void* d_out, int out_size)
{
    const int*   positions = (const int*)  d_in[0];
    const float* hidden    = (const float*)d_in[1];
    const float* w_qkv     = (const float*)d_in[2];
    const float* w_o       = (const float*)d_in[3];
    float*       out       = (float*)d_out;

    float* qkv_ptr  = nullptr;
    float* attn_ptr = nullptr;
    cudaGetSymbolAddress((void**)&qkv_ptr,  g_qkv);
    cudaGetSymbolAddress((void**)&attn_ptr, g_attn);

    cudaFuncSetAttribute(flash_tc_kernel,
                         cudaFuncAttributeMaxDynamicSharedMemorySize,
                         (int)FLASH2_SMEM);

    // 1) QKV projection
    {
        dim3 grid(QKV_COLS / 128, NTOK / 128);
        tf32_gemm_kernel<<<grid, 256>>>(hidden, w_qkv, qkv_ptr, NTOK, QKV_COLS, HIDDEN);
    }

    // 2) prep: rope table, RoPE+scale+split (q,k packed), transpose+split (v packed)
    {
        rope_table_kernel<<<(SS*64 + 255)/256, 256>>>(positions);
        int total = NTOK * 40 * 64;
        prep_qk_kernel<<<(total + 255) / 256, 256>>>();
        dim3 grid(SS/32, D/32, BB*HK);
        prep_v_kernel<<<grid, dim3(32, 8)>>>();
    }

    // 3) tensor-core flash attention
    {
        dim3 grid(SS / 64, H, BB);
        flash_tc_kernel<<<grid, 128, FLASH2_SMEM>>>();
    }

    // 4) output projection
    {
        dim3 grid(HIDDEN / 128, NTOK / 128);
        tf32_gemm_kernel<<<grid, 256>>>(attn_ptr, w_o, out, NTOK, HIDDEN, H*D);
    }
}

// round 14
// speedup vs baseline: 1.0220x; 1.0220x over previous
#include <cuda_runtime.h>
#include <cuda_bf16.h>
#include <math.h>

// Problem constants
#define BB 2
#define SS 2048
#define NTOK (BB*SS)            // 4096
#define HIDDEN 4096
#define H 32
#define HK 8
#define D 128
#define QKV_COLS ((H + 2*HK) * D)   // 6144
#define K_OFF (H*D)                 // 4096
#define V_OFF (H*D + HK*D)          // 5120
#define SCALE 0.08838834764831845f  // 1/sqrt(128)

// Scratch (static device globals — no runtime allocation)
__device__ float g_qkv[(size_t)NTOK * QKV_COLS];   // ~100 MB
__device__ float g_attn[(size_t)NTOK * (H*D)];     // ~67 MB
// RoPE cos/sin table
__device__ float g_cosT[SS * 64];
__device__ float g_sinT[SS * 64];
// pre-split bf16 operands for flash attention
__device__ __nv_bfloat16 g_qh[(size_t)BB*H*SS*D];   // [b,h,s,d]
__device__ __nv_bfloat16 g_ql[(size_t)BB*H*SS*D];
__device__ __nv_bfloat16 g_kh[(size_t)BB*HK*SS*D];  // [b,kvh,s,d]
__device__ __nv_bfloat16 g_kl[(size_t)BB*HK*SS*D];
__device__ __nv_bfloat16 g_vh[(size_t)BB*HK*D*SS];  // [b,kvh,d,s] (transposed)
__device__ __nv_bfloat16 g_vl[(size_t)BB*HK*D*SS];

__device__ __forceinline__ unsigned f2tf32(float x) {
    unsigned r;
    asm("cvt.rna.tf32.f32 %0, %1;" : "=r"(r) : "f"(x));
    return r;
}

// ---------------------------------------------------------------------------
// TF32 tensor-core GEMM (R2/R6-proven): C = A @ B row-major fp32.
// 128x128 block tile, BK=32, 256 threads (8 warps), warp tile 64x32.
// 126 regs -> exactly 2 CTAs/SM; do not perturb.
// ---------------------------------------------------------------------------
#define AS_STRIDE 36
#define BS_STRIDE 136

__global__ __launch_bounds__(256) void tf32_gemm_kernel(
    const float* __restrict__ A, const float* __restrict__ B,
    float* __restrict__ C, int M, int N, int K)
{
    __shared__ float As[128][AS_STRIDE];
    __shared__ float Bs[32][BS_STRIDE];

    const int tid  = threadIdx.x;
    const int wid  = tid >> 5;
    const int lane = tid & 31;
    const int g    = lane >> 2;
    const int tg   = lane & 3;

    const int wm = (wid & 1) * 64;
    const int wn = (wid >> 1) * 32;

    const int bm = blockIdx.y * 128;
    const int bn = blockIdx.x * 128;

    const int arow = tid >> 3;
    const int ac4  = tid & 7;
    const int brow = tid >> 5;
    const int bc4  = tid & 31;

    float acc[4][4][4];
#pragma unroll
    for (int i = 0; i < 4; i++)
#pragma unroll
        for (int j = 0; j < 4; j++)
#pragma unroll
            for (int c = 0; c < 4; c++) acc[i][j][c] = 0.f;

    for (int k0 = 0; k0 < K; k0 += 32) {
#pragma unroll
        for (int p = 0; p < 4; p++) {
            float4 v = *(const float4*)&A[(size_t)(bm + arow + 32*p) * K + k0 + ac4*4];
            v.x = __uint_as_float(f2tf32(v.x));
            v.y = __uint_as_float(f2tf32(v.y));
            v.z = __uint_as_float(f2tf32(v.z));
            v.w = __uint_as_float(f2tf32(v.w));
            *(float4*)&As[arow + 32*p][ac4*4] = v;
        }
#pragma unroll
        for (int p = 0; p < 4; p++) {
            float4 v = *(const float4*)&B[(size_t)(k0 + brow + 8*p) * N + bn + bc4*4];
            v.x = __uint_as_float(f2tf32(v.x));
            v.y = __uint_as_float(f2tf32(v.y));
            v.z = __uint_as_float(f2tf32(v.z));
            v.w = __uint_as_float(f2tf32(v.w));
            *(float4*)&Bs[brow + 8*p][bc4*4] = v;
        }
        __syncthreads();

#pragma unroll
        for (int ks = 0; ks < 4; ks++) {
            unsigned a[4][4], b[4][2];
#pragma unroll
            for (int i = 0; i < 4; i++) {
                const int r = wm + i*16 + g;
                a[i][0] = __float_as_uint(As[r    ][ks*8 + tg    ]);
                a[i][1] = __float_as_uint(As[r + 8][ks*8 + tg    ]);
                a[i][2] = __float_as_uint(As[r    ][ks*8 + tg + 4]);
                a[i][3] = __float_as_uint(As[r + 8][ks*8 + tg + 4]);
            }
#pragma unroll
            for (int j = 0; j < 4; j++) {
                const int c = wn + j*8 + g;
                b[j][0] = __float_as_uint(Bs[ks*8 + tg    ][c]);
                b[j][1] = __float_as_uint(Bs[ks*8 + tg + 4][c]);
            }
#pragma unroll
            for (int i = 0; i < 4; i++)
#pragma unroll
                for (int j = 0; j < 4; j++) {
                    asm volatile(
                        "mma.sync.aligned.m16n8k8.row.col.f32.tf32.tf32.f32 "
                        "{%0,%1,%2,%3}, {%4,%5,%6,%7}, {%8,%9}, {%0,%1,%2,%3};"
                        : "+f"(acc[i][j][0]), "+f"(acc[i][j][1]),
                          "+f"(acc[i][j][2]), "+f"(acc[i][j][3])
                        : "r"(a[i][0]), "r"(a[i][1]), "r"(a[i][2]), "r"(a[i][3]),
                          "r"(b[j][0]), "r"(b[j][1]));
                }
        }
        __syncthreads();
    }

#pragma unroll
    for (int i = 0; i < 4; i++)
#pragma unroll
        for (int j = 0; j < 4; j++) {
            const int row = bm + wm + i*16 + g;
            const int col = bn + wn + j*8 + tg*2;
            float2 v0 = make_float2(acc[i][j][0], acc[i][j][1]);
            float2 v1 = make_float2(acc[i][j][2], acc[i][j][3]);
            *(float2*)&C[(size_t)row       * N + col] = v0;
            *(float2*)&C[(size_t)(row + 8) * N + col] = v1;
        }
}

// ---------------------------------------------------------------------------
// RoPE table
// ---------------------------------------------------------------------------
__global__ __launch_bounds__(256) void rope_table_kernel(const int* __restrict__ positions)
{
    const int idx = blockIdx.x * 256 + threadIdx.x;
    if (idx >= SS * 64) return;
    const int d = idx & 63;
    const int s = idx >> 6;
    const float pos = (float)positions[s];
    const float inv = (float)pow(10000.0, -(double)(2 * d) / 128.0);
    float sn, cn;
    sincosf(pos * inv, &sn, &cn);
    g_cosT[idx] = cn;
    g_sinT[idx] = sn;
}

// ---------------------------------------------------------------------------
// prep_qk: RoPE (table) + (scale for q) + bf16 hi/lo split -> head-major
// ---------------------------------------------------------------------------
__global__ __launch_bounds__(256) void prep_qk_kernel()
{
    const int idx = blockIdx.x * 256 + threadIdx.x;
    const int total = NTOK * 40 * 64;
    if (idx >= total) return;

    const int d  = idx & 63;
    const int h  = (idx >> 6) % 40;
    const int t  = idx / (64 * 40);
    const int b  = t / SS;
    const int s  = t & (SS - 1);

    const float cn = g_cosT[s * 64 + d];
    const float sn = g_sinT[s * 64 + d];

    float x1, x2;
    if (h < H) {
        const float* row = g_qkv + (size_t)t * QKV_COLS + h * D;
        x1 = row[d]; x2 = row[d + 64];
    } else {
        const float* row = g_qkv + (size_t)t * QKV_COLS + K_OFF + (h - H) * D;
        x1 = row[d]; x2 = row[d + 64];
    }
    float y1 = x1 * cn - x2 * sn;
    float y2 = x2 * cn + x1 * sn;

    if (h < H) {
        y1 *= SCALE; y2 *= SCALE;
        const size_t base = ((size_t)(b * H + h) * SS + s) * D;
        __nv_bfloat16 h1 = __float2bfloat16(y1), h2 = __float2bfloat16(y2);
        g_qh[base + d]      = h1;
        g_qh[base + d + 64] = h2;
        g_ql[base + d]      = __float2bfloat16(y1 - __bfloat162float(h1));
        g_ql[base + d + 64] = __float2bfloat16(y2 - __bfloat162float(h2));
    } else {
        const size_t base = ((size_t)(b * HK + (h - H)) * SS + s) * D;
        __nv_bfloat16 h1 = __float2bfloat16(y1), h2 = __float2bfloat16(y2);
        g_kh[base + d]      = h1;
        g_kh[base + d + 64] = h2;
        g_kl[base + d]      = __float2bfloat16(y1 - __bfloat162float(h1));
        g_kl[base + d + 64] = __float2bfloat16(y2 - __bfloat162float(h2));
    }
}

// ---------------------------------------------------------------------------
// prep_v: transpose V to [b,kvh,d,s] with bf16 hi/lo split
// ---------------------------------------------------------------------------
__global__ void prep_v_kernel()
{
    __shared__ float tile[32][33];

    const int s0 = blockIdx.x * 32;
    const int d0 = blockIdx.y * 32;
    const int bk = blockIdx.z;
    const int b  = bk / HK;
    const int kvh = bk % HK;

    const int tx = threadIdx.x;
    const int ty = threadIdx.y;

#pragma unroll
    for (int j = 0; j < 4; j++) {
        const int s = s0 + ty + 8*j;
        tile[ty + 8*j][tx] =
            g_qkv[(size_t)(b*SS + s) * QKV_COLS + V_OFF + kvh*D + d0 + tx];
    }
    __syncthreads();

#pragma unroll
    for (int j = 0; j < 4; j++) {
        const int d = d0 + ty + 8*j;
        const float x = tile[tx][ty + 8*j];
        const size_t o = ((size_t)(b*HK + kvh) * D + d) * SS + s0 + tx;
        __nv_bfloat16 hx = __float2bfloat16(x);
        g_vh[o] = hx;
        g_vl[o] = __float2bfloat16(x - __bfloat162float(hx));
    }
}

// ---------------------------------------------------------------------------
// Flash attention (R11 champion: Q fragments register-hoisted) with
// qt-PAIRING load balance: each CTA does tiles (bx, 31-bx) => uniform 33
// k-iterations per CTA. Per-tile math identical to R11.
// ---------------------------------------------------------------------------
#define QSTR 136
#define VSTR 72
#define FLASH2_SMEM ((4*64*QSTR + 2*128*VSTR) * sizeof(__nv_bfloat16))

__device__ __forceinline__ void mma_bf16(float* c, unsigned a0, unsigned a1,
                                         unsigned a2, unsigned a3,
                                         unsigned b0, unsigned b1)
{
    asm volatile(
        "mma.sync.aligned.m16n8k16.row.col.f32.bf16.bf16.f32 "
        "{%0,%1,%2,%3}, {%4,%5,%6,%7}, {%8,%9}, {%0,%1,%2,%3};"
        : "+f"(c[0]), "+f"(c[1]), "+f"(c[2]), "+f"(c[3])
        : "r"(a0), "r"(a1), "r"(a2), "r"(a3), "r"(b0), "r"(b1));
}

__device__ __forceinline__ unsigned pack2bf(float x, float y) {
    __nv_bfloat162 t = __floats2bfloat162_rn(x, y);
    return *(unsigned*)&t;
}

__global__ __launch_bounds__(128, 2) void flash_tc_kernel()
{
    const int bx = blockIdx.x;        // 0..15 (pair index)
    const int h  = blockIdx.y;
    const int b  = blockIdx.z;
    const int kvh = h >> 2;

    extern __shared__ __nv_bfloat16 sm2[];
    __nv_bfloat16* Qhi = sm2;
    __nv_bfloat16* Qlo = Qhi + 64*QSTR;
    __nv_bfloat16* Khi = Qlo + 64*QSTR;
    __nv_bfloat16* Klo = Khi + 64*QSTR;
    __nv_bfloat16* Vth = Klo + 64*QSTR;
    __nv_bfloat16* Vtl = Vth + 128*VSTR;

    const int tid  = threadIdx.x;
    const int warp = tid >> 5;
    const int lane = tid & 31;
    const int g    = lane >> 2;
    const int tg   = lane & 3;

    const int row0 = warp*16 + g;

    const __nv_bfloat16* kh_base = g_kh + (size_t)(b*HK + kvh) * SS * D;
    const __nv_bfloat16* kl_base = g_kl + (size_t)(b*HK + kvh) * SS * D;
    const __nv_bfloat16* vh_base = g_vh + (size_t)(b*HK + kvh) * D * SS;
    const __nv_bfloat16* vl_base = g_vl + (size_t)(b*HK + kvh) * D * SS;

#pragma unroll 1
    for (int half = 0; half < 2; half++) {
        const int qt = half ? (31 - bx) : bx;

        // ---- stage Q for this tile (pure uint4 copies) ----
        __syncthreads();   // prior tile's Q-fragment reads are long done; guards smem reuse
        {
            const __nv_bfloat16* srcs[2] = {
                g_qh + ((size_t)(b*H + h) * SS + qt*64) * D,
                g_ql + ((size_t)(b*H + h) * SS + qt*64) * D };
            __nv_bfloat16* dsts[2] = { Qhi, Qlo };
#pragma unroll
            for (int a = 0; a < 2; a++)
                for (int i = tid; i < 64*16; i += 128) {
                    const int row = i >> 4, c8 = i & 15;
                    *(uint4*)&dsts[a][row*QSTR + c8*8] =
                        *(const uint4*)&srcs[a][(size_t)row*D + c8*8];
                }
        }
        __syncthreads();

        // ---- hoist Q fragments to registers ----
        unsigned qf[8][8];
#pragma unroll
        for (int kc = 0; kc < 8; kc++) {
            const int ko = kc*16 + tg*2;
            qf[kc][0] = *(unsigned*)&Qhi[(row0    )*QSTR + ko];
            qf[kc][1] = *(unsigned*)&Qhi[(row0 + 8)*QSTR + ko];
            qf[kc][2] = *(unsigned*)&Qhi[(row0    )*QSTR + ko + 8];
            qf[kc][3] = *(unsigned*)&Qhi[(row0 + 8)*QSTR + ko + 8];
            qf[kc][4] = *(unsigned*)&Qlo[(row0    )*QSTR + ko];
            qf[kc][5] = *(unsigned*)&Qlo[(row0 + 8)*QSTR + ko];
            qf[kc][6] = *(unsigned*)&Qlo[(row0    )*QSTR + ko + 8];
            qf[kc][7] = *(unsigned*)&Qlo[(row0 + 8)*QSTR + ko + 8];
        }

        float m0 = -1e30f, m1 = -1e30f, l0 = 0.f, l1 = 0.f;
        float oAcc[16][4];
#pragma unroll
        for (int dt = 0; dt < 16; dt++)
#pragma unroll
            for (int c = 0; c < 4; c++) oAcc[dt][c] = 0.f;

        for (int kt = 0; kt <= qt; kt++) {
            __syncthreads();
            for (int i = tid; i < 64*16; i += 128) {
                const int row = i >> 4, c8 = i & 15;
                const size_t src = (size_t)(kt*64 + row) * D + c8*8;
                *(uint4*)&Khi[row*QSTR + c8*8] = *(const uint4*)&kh_base[src];
                *(uint4*)&Klo[row*QSTR + c8*8] = *(const uint4*)&kl_base[src];
            }
            for (int i = tid; i < 128*8; i += 128) {
                const int d = i >> 3, s8 = i & 7;
                const size_t src = (size_t)d * SS + kt*64 + s8*8;
                *(uint4*)&Vth[d*VSTR + s8*8] = *(const uint4*)&vh_base[src];
                *(uint4*)&Vtl[d*VSTR + s8*8] = *(const uint4*)&vl_base[src];
            }
            __syncthreads();

            float sAcc[8][4];
#pragma unroll
            for (int nt = 0; nt < 8; nt++)
#pragma unroll
                for (int c = 0; c < 4; c++) sAcc[nt][c] = 0.f;

#pragma unroll
            for (int kc = 0; kc < 8; kc++) {
                const int ko = kc*16 + tg*2;
#pragma unroll
                for (int nt = 0; nt < 8; nt++) {
                    const int krow = (nt*8 + g)*QSTR + ko;
                    unsigned bh0 = *(unsigned*)&Khi[krow];
                    unsigned bh1 = *(unsigned*)&Khi[krow + 8];
                    unsigned bl0 = *(unsigned*)&Klo[krow];
                    unsigned bl1 = *(unsigned*)&Klo[krow + 8];
                    mma_bf16(sAcc[nt], qf[kc][0], qf[kc][1], qf[kc][2], qf[kc][3], bh0, bh1);
                    mma_bf16(sAcc[nt], qf[kc][0], qf[kc][1], qf[kc][2], qf[kc][3], bl0, bl1);
                    mma_bf16(sAcc[nt], qf[kc][4], qf[kc][5], qf[kc][6], qf[kc][7], bh0, bh1);
                }
            }

            if (kt == qt) {
#pragma unroll
                for (int nt = 0; nt < 8; nt++) {
                    const int col = nt*8 + tg*2;
                    if (col     > row0    ) sAcc[nt][0] = -1e30f;
                    if (col + 1 > row0    ) sAcc[nt][1] = -1e30f;
                    if (col     > row0 + 8) sAcc[nt][2] = -1e30f;
                    if (col + 1 > row0 + 8) sAcc[nt][3] = -1e30f;
                }
            }

            float mt0 = -1e30f, mt1 = -1e30f;
#pragma unroll
            for (int nt = 0; nt < 8; nt++) {
                mt0 = fmaxf(mt0, fmaxf(sAcc[nt][0], sAcc[nt][1]));
                mt1 = fmaxf(mt1, fmaxf(sAcc[nt][2], sAcc[nt][3]));
            }
            mt0 = fmaxf(mt0, __shfl_xor_sync(0xffffffffu, mt0, 1));
            mt0 = fmaxf(mt0, __shfl_xor_sync(0xffffffffu, mt0, 2));
            mt1 = fmaxf(mt1, __shfl_xor_sync(0xffffffffu, mt1, 1));
            mt1 = fmaxf(mt1, __shfl_xor_sync(0xffffffffu, mt1, 2));

            const float mn0 = fmaxf(m0, mt0);
            const float mn1 = fmaxf(m1, mt1);
            const float cr0 = __expf(m0 - mn0);
            const float cr1 = __expf(m1 - mn1);

            float sum0 = 0.f, sum1 = 0.f;
#pragma unroll
            for (int nt = 0; nt < 8; nt++) {
                sAcc[nt][0] = __expf(sAcc[nt][0] - mn0);
                sAcc[nt][1] = __expf(sAcc[nt][1] - mn0);
                sAcc[nt][2] = __expf(sAcc[nt][2] - mn1);
                sAcc[nt][3] = __expf(sAcc[nt][3] - mn1);
                sum0 += sAcc[nt][0] + sAcc[nt][1];
                sum1 += sAcc[nt][2] + sAcc[nt][3];
            }
            l0 = l0 * cr0 + sum0;
            l1 = l1 * cr1 + sum1;
            m0 = mn0; m1 = mn1;

#pragma unroll
            for (int dt = 0; dt < 16; dt++) {
                oAcc[dt][0] *= cr0; oAcc[dt][1] *= cr0;
                oAcc[dt][2] *= cr1; oAcc[dt][3] *= cr1;
            }

#pragma unroll
            for (int kc = 0; kc < 4; kc++) {
                float p00 = sAcc[2*kc][0],   p01 = sAcc[2*kc][1];
                float p02 = sAcc[2*kc][2],   p03 = sAcc[2*kc][3];
                float p10 = sAcc[2*kc+1][0], p11 = sAcc[2*kc+1][1];
                float p12 = sAcc[2*kc+1][2], p13 = sAcc[2*kc+1][3];

                __nv_bfloat16 h00=__float2bfloat16(p00), h01=__float2bfloat16(p01);
                __nv_bfloat16 h02=__float2bfloat16(p02), h03=__float2bfloat16(p03);
                __nv_bfloat16 h10=__float2bfloat16(p10), h11=__float2bfloat16(p11);
                __nv_bfloat16 h12=__float2bfloat16(p12), h13=__float2bfloat16(p13);

                __nv_bfloat162 t0(h00,h01), t1(h02,h03), t2(h10,h11), t3(h12,h13);
                unsigned ah0 = *(unsigned*)&t0;
                unsigned ah1 = *(unsigned*)&t1;
                unsigned ah2 = *(unsigned*)&t2;
                unsigned ah3 = *(unsigned*)&t3;

                unsigned al0 = pack2bf(p00 - __bfloat162float(h00), p01 - __bfloat162float(h01));
                unsigned al1 = pack2bf(p02 - __bfloat162float(h02), p03 - __bfloat162float(h03));
                unsigned al2 = pack2bf(p10 - __bfloat162float(h10), p11 - __bfloat162float(h11));
                unsigned al3 = pack2bf(p12 - __bfloat162float(h12), p13 - __bfloat162float(h13));

#pragma unroll
                for (int dt = 0; dt < 16; dt++) {
                    const int vrow = (dt*8 + g)*VSTR + kc*16 + tg*2;
                    unsigned bh0 = *(unsigned*)&Vth[vrow];
                    unsigned bh1 = *(unsigned*)&Vth[vrow + 8];
                    unsigned bl0 = *(unsigned*)&Vtl[vrow];
                    unsigned bl1 = *(unsigned*)&Vtl[vrow + 8];
                    mma_bf16(oAcc[dt], ah0, ah1, ah2, ah3, bh0, bh1);
                    mma_bf16(oAcc[dt], ah0, ah1, ah2, ah3, bl0, bl1);
                    mma_bf16(oAcc[dt], al0, al1, al2, al3, bh0, bh1);
                }
            }
        }

        // ---- finalize this tile ----
        l0 += __shfl_xor_sync(0xffffffffu, l0, 1);
        l0 += __shfl_xor_sync(0xffffffffu, l0, 2);
        l1 += __shfl_xor_sync(0xffffffffu, l1, 1);
        l1 += __shfl_xor_sync(0xffffffffu, l1, 2);
        const float inv0 = 1.f / l0;
        const float inv1 = 1.f / l1;

        const int tok0 = b*SS + qt*64 + row0;
#pragma unroll
        for (int dt = 0; dt < 16; dt++) {
            const int col = h*D + dt*8 + tg*2;
            float2 v0 = make_float2(oAcc[dt][0]*inv0, oAcc[dt][1]*inv0);
            float2 v1 = make_float2(oAcc[dt][2]*inv1, oAcc[dt][3]*inv1);
            *(float2*)&g_attn[(size_t)tok0       * (H*D) + col] = v0;
            *(float2*)&g_attn[(size_t)(tok0 + 8) * (H*D) + col] = v1;
        }
    }
}

// ---------------------------------------------------------------------------
// launch
// ---------------------------------------------------------------------------
extern "C" void kernel_launch(void* const* d_in, const int* in_sizes, int n_in,
                              void* d_out, int out_size)
{
    const int*   positions = (const int*)  d_in[0];
    const float* hidden    = (const float*)d_in[1];
    const float* w_qkv     = (const float*)d_in[2];
    const float* w_o       = (const float*)d_in[3];
    float*       out       = (float*)d_out;

    float* qkv_ptr  = nullptr;
    float* attn_ptr = nullptr;
    cudaGetSymbolAddress((void**)&qkv_ptr,  g_qkv);
    cudaGetSymbolAddress((void**)&attn_ptr, g_attn);

    cudaFuncSetAttribute(flash_tc_kernel,
                         cudaFuncAttributeMaxDynamicSharedMemorySize,
                         (int)FLASH2_SMEM);

    // 0) rope table (depends only on positions; off the GEMM->prep critical path)
    rope_table_kernel<<<(SS*64 + 255)/256, 256>>>(positions);

    // 1) QKV projection
    {
        dim3 grid(QKV_COLS / 128, NTOK / 128);
        tf32_gemm_kernel<<<grid, 256>>>(hidden, w_qkv, qkv_ptr, NTOK, QKV_COLS, HIDDEN);
    }

    // 2) prep: RoPE+scale+split (q,k), transpose+split (v)
    {
        int total = NTOK * 40 * 64;
        prep_qk_kernel<<<(total + 255) / 256, 256>>>();
        dim3 grid(SS/32, D/32, BB*HK);
        prep_v_kernel<<<grid, dim3(32, 8)>>>();
    }

    // 3) tensor-core flash attention (qt-paired load balance)
    {
        dim3 grid(SS / 128, H, BB);   // 16 x 32 x 2
        flash_tc_kernel<<<grid, 128, FLASH2_SMEM>>>();
    }

    // 4) output projection
    {
        dim3 grid(HIDDEN / 128, NTOK / 128);
        tf32_gemm_kernel<<<grid, 256>>>(attn_ptr, w_o, out, NTOK, HIDDEN, H*D);
    }
}

// round 15
// speedup vs baseline: 1.0640x; 1.0412x over previous
#include <cuda_runtime.h>
#include <cuda_bf16.h>
#include <math.h>

// Problem constants
#define BB 2
#define SS 2048
#define NTOK (BB*SS)            // 4096
#define HIDDEN 4096
#define H 32
#define HK 8
#define D 128
#define QKV_COLS ((H + 2*HK) * D)   // 6144
#define K_OFF (H*D)                 // 4096
#define V_OFF (H*D + HK*D)          // 5120
#define SCALE 0.08838834764831845f  // 1/sqrt(128)

// Scratch (static device globals — no runtime allocation)
__device__ float g_qkv[(size_t)NTOK * QKV_COLS];   // ~100 MB
__device__ float g_attn[(size_t)NTOK * (H*D)];     // ~67 MB
// RoPE cos/sin table
__device__ float g_cosT[SS * 64];
__device__ float g_sinT[SS * 64];
// pre-split bf16 operands for flash attention
__device__ __nv_bfloat16 g_qh[(size_t)BB*H*SS*D];   // [b,h,s,d]
__device__ __nv_bfloat16 g_ql[(size_t)BB*H*SS*D];
__device__ __nv_bfloat16 g_kh[(size_t)BB*HK*SS*D];  // [b,kvh,s,d]
__device__ __nv_bfloat16 g_kl[(size_t)BB*HK*SS*D];
__device__ __nv_bfloat16 g_vh[(size_t)BB*HK*D*SS];  // [b,kvh,d,s] (transposed)
__device__ __nv_bfloat16 g_vl[(size_t)BB*HK*D*SS];

__device__ __forceinline__ unsigned f2tf32(float x) {
    unsigned r;
    asm("cvt.rna.tf32.f32 %0, %1;" : "=r"(r) : "f"(x));
    return r;
}

// ---------------------------------------------------------------------------
// TF32 tensor-core GEMM: 128x128 block tile, BK=32, 128 threads (4 warps),
// warp tile 64x64. 2 CTAs/SM by design (__launch_bounds__(128,2); ~190 regs).
// Fragment smem traffic 3.9 B/output vs 5.9 in the 8-warp 64x32 version.
// Numerics identical (same cvt.rna staging, same k order, same MMA shape).
// ---------------------------------------------------------------------------
#define AS_STRIDE 36
#define BS_STRIDE 136

__global__ __launch_bounds__(128, 2) void tf32_gemm_kernel(
    const float* __restrict__ A, const float* __restrict__ B,
    float* __restrict__ C, int M, int N, int K)
{
    __shared__ float As[128][AS_STRIDE];
    __shared__ float Bs[32][BS_STRIDE];

    const int tid  = threadIdx.x;
    const int wid  = tid >> 5;
    const int lane = tid & 31;
    const int g    = lane >> 2;
    const int tg   = lane & 3;

    const int wm = (wid & 1) * 64;       // 2x2 warp grid
    const int wn = (wid >> 1) * 64;

    const int bm = blockIdx.y * 128;
    const int bn = blockIdx.x * 128;

    const int arow = tid >> 3;           // 0..15 (8 passes of 16 rows)
    const int ac4  = tid & 7;            // k/4
    const int brow = tid >> 5;           // 0..3 (8 passes of 4 rows)
    const int bc4  = tid & 31;           // n/4

    float acc[4][8][4];
#pragma unroll
    for (int i = 0; i < 4; i++)
#pragma unroll
        for (int j = 0; j < 8; j++)
#pragma unroll
            for (int c = 0; c < 4; c++) acc[i][j][c] = 0.f;

    for (int k0 = 0; k0 < K; k0 += 32) {
        // stage A tile 128x32 (tf32-convert)
#pragma unroll
        for (int p = 0; p < 8; p++) {
            float4 v = *(const float4*)&A[(size_t)(bm + arow + 16*p) * K + k0 + ac4*4];
            v.x = __uint_as_float(f2tf32(v.x));
            v.y = __uint_as_float(f2tf32(v.y));
            v.z = __uint_as_float(f2tf32(v.z));
            v.w = __uint_as_float(f2tf32(v.w));
            *(float4*)&As[arow + 16*p][ac4*4] = v;
        }
        // stage B tile 32x128
#pragma unroll
        for (int p = 0; p < 8; p++) {
            float4 v = *(const float4*)&B[(size_t)(k0 + brow + 4*p) * N + bn + bc4*4];
            v.x = __uint_as_float(f2tf32(v.x));
            v.y = __uint_as_float(f2tf32(v.y));
            v.z = __uint_as_float(f2tf32(v.z));
            v.w = __uint_as_float(f2tf32(v.w));
            *(float4*)&Bs[brow + 4*p][bc4*4] = v;
        }
        __syncthreads();

#pragma unroll
        for (int ks = 0; ks < 4; ks++) {
            unsigned a[4][4], b[8][2];
#pragma unroll
            for (int i = 0; i < 4; i++) {
                const int r = wm + i*16 + g;
                a[i][0] = __float_as_uint(As[r    ][ks*8 + tg    ]);
                a[i][1] = __float_as_uint(As[r + 8][ks*8 + tg    ]);
                a[i][2] = __float_as_uint(As[r    ][ks*8 + tg + 4]);
                a[i][3] = __float_as_uint(As[r + 8][ks*8 + tg + 4]);
            }
#pragma unroll
            for (int j = 0; j < 8; j++) {
                const int c = wn + j*8 + g;
                b[j][0] = __float_as_uint(Bs[ks*8 + tg    ][c]);
                b[j][1] = __float_as_uint(Bs[ks*8 + tg + 4][c]);
            }
#pragma unroll
            for (int i = 0; i < 4; i++)
#pragma unroll
                for (int j = 0; j < 8; j++) {
                    asm volatile(
                        "mma.sync.aligned.m16n8k8.row.col.f32.tf32.tf32.f32 "
                        "{%0,%1,%2,%3}, {%4,%5,%6,%7}, {%8,%9}, {%0,%1,%2,%3};"
                        : "+f"(acc[i][j][0]), "+f"(acc[i][j][1]),
                          "+f"(acc[i][j][2]), "+f"(acc[i][j][3])
                        : "r"(a[i][0]), "r"(a[i][1]), "r"(a[i][2]), "r"(a[i][3]),
                          "r"(b[j][0]), "r"(b[j][1]));
                }
        }
        __syncthreads();
    }

#pragma unroll
    for (int i = 0; i < 4; i++)
#pragma unroll
        for (int j = 0; j < 8; j++) {
            const int row = bm + wm + i*16 + g;
            const int col = bn + wn + j*8 + tg*2;
            float2 v0 = make_float2(acc[i][j][0], acc[i][j][1]);
            float2 v1 = make_float2(acc[i][j][2], acc[i][j][3]);
            *(float2*)&C[(size_t)row       * N + col] = v0;
            *(float2*)&C[(size_t)(row + 8) * N + col] = v1;
        }
}

// ---------------------------------------------------------------------------
// RoPE table
// ---------------------------------------------------------------------------
__global__ __launch_bounds__(256) void rope_table_kernel(const int* __restrict__ positions)
{
    const int idx = blockIdx.x * 256 + threadIdx.x;
    if (idx >= SS * 64) return;
    const int d = idx & 63;
    const int s = idx >> 6;
    const float pos = (float)positions[s];
    const float inv = (float)pow(10000.0, -(double)(2 * d) / 128.0);
    float sn, cn;
    sincosf(pos * inv, &sn, &cn);
    g_cosT[idx] = cn;
    g_sinT[idx] = sn;
}

// ---------------------------------------------------------------------------
// prep_qk: RoPE (table) + (scale for q) + bf16 hi/lo split -> head-major
// ---------------------------------------------------------------------------
__global__ __launch_bounds__(256) void prep_qk_kernel()
{
    const int idx = blockIdx.x * 256 + threadIdx.x;
    const int total = NTOK * 40 * 64;
    if (idx >= total) return;

    const int d  = idx & 63;
    const int h  = (idx >> 6) % 40;
    const int t  = idx / (64 * 40);
    const int b  = t / SS;
    const int s  = t & (SS - 1);

    const float cn = g_cosT[s * 64 + d];
    const float sn = g_sinT[s * 64 + d];

    float x1, x2;
    if (h < H) {
        const float* row = g_qkv + (size_t)t * QKV_COLS + h * D;
        x1 = row[d]; x2 = row[d + 64];
    } else {
        const float* row = g_qkv + (size_t)t * QKV_COLS + K_OFF + (h - H) * D;
        x1 = row[d]; x2 = row[d + 64];
    }
    float y1 = x1 * cn - x2 * sn;
    float y2 = x2 * cn + x1 * sn;

    if (h < H) {
        y1 *= SCALE; y2 *= SCALE;
        const size_t base = ((size_t)(b * H + h) * SS + s) * D;
        __nv_bfloat16 h1 = __float2bfloat16(y1), h2 = __float2bfloat16(y2);
        g_qh[base + d]      = h1;
        g_qh[base + d + 64] = h2;
        g_ql[base + d]      = __float2bfloat16(y1 - __bfloat162float(h1));
        g_ql[base + d + 64] = __float2bfloat16(y2 - __bfloat162float(h2));
    } else {
        const size_t base = ((size_t)(b * HK + (h - H)) * SS + s) * D;
        __nv_bfloat16 h1 = __float2bfloat16(y1), h2 = __float2bfloat16(y2);
        g_kh[base + d]      = h1;
        g_kh[base + d + 64] = h2;
        g_kl[base + d]      = __float2bfloat16(y1 - __bfloat162float(h1));
        g_kl[base + d + 64] = __float2bfloat16(y2 - __bfloat162float(h2));
    }
}

// ---------------------------------------------------------------------------
// prep_v: transpose V to [b,kvh,d,s] with bf16 hi/lo split
// ---------------------------------------------------------------------------
__global__ void prep_v_kernel()
{
    __shared__ float tile[32][33];

    const int s0 = blockIdx.x * 32;
    const int d0 = blockIdx.y * 32;
    const int bk = blockIdx.z;
    const int b  = bk / HK;
    const int kvh = bk % HK;

    const int tx = threadIdx.x;
    const int ty = threadIdx.y;

#pragma unroll
    for (int j = 0; j < 4; j++) {
        const int s = s0 + ty + 8*j;
        tile[ty + 8*j][tx] =
            g_qkv[(size_t)(b*SS + s) * QKV_COLS + V_OFF + kvh*D + d0 + tx];
    }
    __syncthreads();

#pragma unroll
    for (int j = 0; j < 4; j++) {
        const int d = d0 + ty + 8*j;
        const float x = tile[tx][ty + 8*j];
        const size_t o = ((size_t)(b*HK + kvh) * D + d) * SS + s0 + tx;
        __nv_bfloat16 hx = __float2bfloat16(x);
        g_vh[o] = hx;
        g_vl[o] = __float2bfloat16(x - __bfloat162float(hx));
    }
}

// ---------------------------------------------------------------------------
// Flash attention (R11 champion: Q fragments register-hoisted)
// ---------------------------------------------------------------------------
#define QSTR 136
#define VSTR 72
#define FLASH2_SMEM ((4*64*QSTR + 2*128*VSTR) * sizeof(__nv_bfloat16))

__device__ __forceinline__ void mma_bf16(float* c, unsigned a0, unsigned a1,
                                         unsigned a2, unsigned a3,
                                         unsigned b0, unsigned b1)
{
    asm volatile(
        "mma.sync.aligned.m16n8k16.row.col.f32.bf16.bf16.f32 "
        "{%0,%1,%2,%3}, {%4,%5,%6,%7}, {%8,%9}, {%0,%1,%2,%3};"
        : "+f"(c[0]), "+f"(c[1]), "+f"(c[2]), "+f"(c[3])
        : "r"(a0), "r"(a1), "r"(a2), "r"(a3), "r"(b0), "r"(b1));
}

__device__ __forceinline__ unsigned pack2bf(float x, float y) {
    __nv_bfloat162 t = __floats2bfloat162_rn(x, y);
    return *(unsigned*)&t;
}

__global__ __launch_bounds__(128, 2) void flash_tc_kernel()
{
    const int qt = blockIdx.x;
    const int h  = blockIdx.y;
    const int b  = blockIdx.z;
    const int kvh = h >> 2;

    extern __shared__ __nv_bfloat16 sm2[];
    __nv_bfloat16* Qhi = sm2;
    __nv_bfloat16* Qlo = Qhi + 64*QSTR;
    __nv_bfloat16* Khi = Qlo + 64*QSTR;
    __nv_bfloat16* Klo = Khi + 64*QSTR;
    __nv_bfloat16* Vth = Klo + 64*QSTR;
    __nv_bfloat16* Vtl = Vth + 128*VSTR;

    const int tid  = threadIdx.x;
    const int warp = tid >> 5;
    const int lane = tid & 31;
    const int g    = lane >> 2;
    const int tg   = lane & 3;

    {
        const __nv_bfloat16* srcs[2] = {
            g_qh + ((size_t)(b*H + h) * SS + qt*64) * D,
            g_ql + ((size_t)(b*H + h) * SS + qt*64) * D };
        __nv_bfloat16* dsts[2] = { Qhi, Qlo };
#pragma unroll
        for (int a = 0; a < 2; a++)
            for (int i = tid; i < 64*16; i += 128) {
                const int row = i >> 4, c8 = i & 15;
                *(uint4*)&dsts[a][row*QSTR + c8*8] =
                    *(const uint4*)&srcs[a][(size_t)row*D + c8*8];
            }
    }
    __syncthreads();

    const int row0 = warp*16 + g;

    unsigned qf[8][8];
#pragma unroll
    for (int kc = 0; kc < 8; kc++) {
        const int ko = kc*16 + tg*2;
        qf[kc][0] = *(unsigned*)&Qhi[(row0    )*QSTR + ko];
        qf[kc][1] = *(unsigned*)&Qhi[(row0 + 8)*QSTR + ko];
        qf[kc][2] = *(unsigned*)&Qhi[(row0    )*QSTR + ko + 8];
        qf[kc][3] = *(unsigned*)&Qhi[(row0 + 8)*QSTR + ko + 8];
        qf[kc][4] = *(unsigned*)&Qlo[(row0    )*QSTR + ko];
        qf[kc][5] = *(unsigned*)&Qlo[(row0 + 8)*QSTR + ko];
        qf[kc][6] = *(unsigned*)&Qlo[(row0    )*QSTR + ko + 8];
        qf[kc][7] = *(unsigned*)&Qlo[(row0 + 8)*QSTR + ko + 8];
    }

    float m0 = -1e30f, m1 = -1e30f, l0 = 0.f, l1 = 0.f;
    float oAcc[16][4];
#pragma unroll
    for (int dt = 0; dt < 16; dt++)
#pragma unroll
        for (int c = 0; c < 4; c++) oAcc[dt][c] = 0.f;

    const __nv_bfloat16* kh_base = g_kh + (size_t)(b*HK + kvh) * SS * D;
    const __nv_bfloat16* kl_base = g_kl + (size_t)(b*HK + kvh) * SS * D;
    const __nv_bfloat16* vh_base = g_vh + (size_t)(b*HK + kvh) * D * SS;
    const __nv_bfloat16* vl_base = g_vl + (size_t)(b*HK + kvh) * D * SS;

    for (int kt = 0; kt <= qt; kt++) {
        __syncthreads();
        for (int i = tid; i < 64*16; i += 128) {
            const int row = i >> 4, c8 = i & 15;
            const size_t src = (size_t)(kt*64 + row) * D + c8*8;
            *(uint4*)&Khi[row*QSTR + c8*8] = *(const uint4*)&kh_base[src];
            *(uint4*)&Klo[row*QSTR + c8*8] = *(const uint4*)&kl_base[src];
        }
        for (int i = tid; i < 128*8; i += 128) {
            const int d = i >> 3, s8 = i & 7;
            const size_t src = (size_t)d * SS + kt*64 + s8*8;
            *(uint4*)&Vth[d*VSTR + s8*8] = *(const uint4*)&vh_base[src];
            *(uint4*)&Vtl[d*VSTR + s8*8] = *(const uint4*)&vl_base[src];
        }
        __syncthreads();

        float sAcc[8][4];
#pragma unroll
        for (int nt = 0; nt < 8; nt++)
#pragma unroll
            for (int c = 0; c < 4; c++) sAcc[nt][c] = 0.f;

#pragma unroll
        for (int kc = 0; kc < 8; kc++) {
            const int ko = kc*16 + tg*2;
#pragma unroll
            for (int nt = 0; nt < 8; nt++) {
                const int krow = (nt*8 + g)*QSTR + ko;
                unsigned bh0 = *(unsigned*)&Khi[krow];
                unsigned bh1 = *(unsigned*)&Khi[krow + 8];
                unsigned bl0 = *(unsigned*)&Klo[krow];
                unsigned bl1 = *(unsigned*)&Klo[krow + 8];
                mma_bf16(sAcc[nt], qf[kc][0], qf[kc][1], qf[kc][2], qf[kc][3], bh0, bh1);
                mma_bf16(sAcc[nt], qf[kc][0], qf[kc][1], qf[kc][2], qf[kc][3], bl0, bl1);
                mma_bf16(sAcc[nt], qf[kc][4], qf[kc][5], qf[kc][6], qf[kc][7], bh0, bh1);
            }
        }

        if (kt == qt) {
#pragma unroll
            for (int nt = 0; nt < 8; nt++) {
                const int col = nt*8 + tg*2;
                if (col     > row0    ) sAcc[nt][0] = -1e30f;
                if (col + 1 > row0    ) sAcc[nt][1] = -1e30f;
                if (col     > row0 + 8) sAcc[nt][2] = -1e30f;
                if (col + 1 > row0 + 8) sAcc[nt][3] = -1e30f;
            }
        }

        float mt0 = -1e30f, mt1 = -1e30f;
#pragma unroll
        for (int nt = 0; nt < 8; nt++) {
            mt0 = fmaxf(mt0, fmaxf(sAcc[nt][0], sAcc[nt][1]));
            mt1 = fmaxf(mt1, fmaxf(sAcc[nt][2], sAcc[nt][3]));
        }
        mt0 = fmaxf(mt0, __shfl_xor_sync(0xffffffffu, mt0, 1));
        mt0 = fmaxf(mt0, __shfl_xor_sync(0xffffffffu, mt0, 2));
        mt1 = fmaxf(mt1, __shfl_xor_sync(0xffffffffu, mt1, 1));
        mt1 = fmaxf(mt1, __shfl_xor_sync(0xffffffffu, mt1, 2));

        const float mn0 = fmaxf(m0, mt0);
        const float mn1 = fmaxf(m1, mt1);
        const float cr0 = __expf(m0 - mn0);
        const float cr1 = __expf(m1 - mn1);

        float sum0 = 0.f, sum1 = 0.f;
#pragma unroll
        for (int nt = 0; nt < 8; nt++) {
            sAcc[nt][0] = __expf(sAcc[nt][0] - mn0);
            sAcc[nt][1] = __expf(sAcc[nt][1] - mn0);
            sAcc[nt][2] = __expf(sAcc[nt][2] - mn1);
            sAcc[nt][3] = __expf(sAcc[nt][3] - mn1);
            sum0 += sAcc[nt][0] + sAcc[nt][1];
            sum1 += sAcc[nt][2] + sAcc[nt][3];
        }
        l0 = l0 * cr0 + sum0;
        l1 = l1 * cr1 + sum1;
        m0 = mn0; m1 = mn1;

#pragma unroll
        for (int dt = 0; dt < 16; dt++) {
            oAcc[dt][0] *= cr0; oAcc[dt][1] *= cr0;
            oAcc[dt][2] *= cr1; oAcc[dt][3] *= cr1;
        }

#pragma unroll
        for (int kc = 0; kc < 4; kc++) {
            float p00 = sAcc[2*kc][0],   p01 = sAcc[2*kc][1];
            float p02 = sAcc[2*kc][2],   p03 = sAcc[2*kc][3];
            float p10 = sAcc[2*kc+1][0], p11 = sAcc[2*kc+1][1];
            float p12 = sAcc[2*kc+1][2], p13 = sAcc[2*kc+1][3];

            __nv_bfloat16 h00=__float2bfloat16(p00), h01=__float2bfloat16(p01);
            __nv_bfloat16 h02=__float2bfloat16(p02), h03=__float2bfloat16(p03);
            __nv_bfloat16 h10=__float2bfloat16(p10), h11=__float2bfloat16(p11);
            __nv_bfloat16 h12=__float2bfloat16(p12), h13=__float2bfloat16(p13);

            __nv_bfloat162 t0(h00,h01), t1(h02,h03), t2(h10,h11), t3(h12,h13);
            unsigned ah0 = *(unsigned*)&t0;
            unsigned ah1 = *(unsigned*)&t1;
            unsigned ah2 = *(unsigned*)&t2;
            unsigned ah3 = *(unsigned*)&t3;

            unsigned al0 = pack2bf(p00 - __bfloat162float(h00), p01 - __bfloat162float(h01));
            unsigned al1 = pack2bf(p02 - __bfloat162float(h02), p03 - __bfloat162float(h03));
            unsigned al2 = pack2bf(p10 - __bfloat162float(h10), p11 - __bfloat162float(h11));
            unsigned al3 = pack2bf(p12 - __bfloat162float(h12), p13 - __bfloat162float(h13));

#pragma unroll
            for (int dt = 0; dt < 16; dt++) {
                const int vrow = (dt*8 + g)*VSTR + kc*16 + tg*2;
                unsigned bh0 = *(unsigned*)&Vth[vrow];
                unsigned bh1 = *(unsigned*)&Vth[vrow + 8];
                unsigned bl0 = *(unsigned*)&Vtl[vrow];
                unsigned bl1 = *(unsigned*)&Vtl[vrow + 8];
                mma_bf16(oAcc[dt], ah0, ah1, ah2, ah3, bh0, bh1);
                mma_bf16(oAcc[dt], ah0, ah1, ah2, ah3, bl0, bl1);
                mma_bf16(oAcc[dt], al0, al1, al2, al3, bh0, bh1);
            }
        }
    }

    l0 += __shfl_xor_sync(0xffffffffu, l0, 1);
    l0 += __shfl_xor_sync(0xffffffffu, l0, 2);
    l1 += __shfl_xor_sync(0xffffffffu, l1, 1);
    l1 += __shfl_xor_sync(0xffffffffu, l1, 2);
    const float inv0 = 1.f / l0;
    const float inv1 = 1.f / l1;

    const int tok0 = b*SS + qt*64 + row0;
#pragma unroll
    for (int dt = 0; dt < 16; dt++) {
        const int col = h*D + dt*8 + tg*2;
        float2 v0 = make_float2(oAcc[dt][0]*inv0, oAcc[dt][1]*inv0);
        float2 v1 = make_float2(oAcc[dt][2]*inv1, oAcc[dt][3]*inv1);
        *(float2*)&g_attn[(size_t)tok0       * (H*D) + col] = v0;
        *(float2*)&g_attn[(size_t)(tok0 + 8) * (H*D) + col] = v1;
    }
}

// ---------------------------------------------------------------------------
// launch
// ---------------------------------------------------------------------------
extern "C" void kernel_launch(void* const* d_in, const int* in_sizes, int n_in,
                              void* d_out, int out_size)
{
    const int*   positions = (const int*)  d_in[0];
    const float* hidden    = (const float*)d_in[1];
    const float* w_qkv     = (const float*)d_in[2];
    const float* w_o       = (const float*)d_in[3];
    float*       out       = (float*)d_out;

    float* qkv_ptr  = nullptr;
    float* attn_ptr = nullptr;
    cudaGetSymbolAddress((void**)&qkv_ptr,  g_qkv);
    cudaGetSymbolAddress((void**)&attn_ptr, g_attn);

    cudaFuncSetAttribute(flash_tc_kernel,
                         cudaFuncAttributeMaxDynamicSharedMemorySize,
                         (int)FLASH2_SMEM);

    // 0) rope table (depends only on positions)
    rope_table_kernel<<<(SS*64 + 255)/256, 256>>>(positions);

    // 1) QKV projection
    {
        dim3 grid(QKV_COLS / 128, NTOK / 128);
        tf32_gemm_kernel<<<grid, 128>>>(hidden, w_qkv, qkv_ptr, NTOK, QKV_COLS, HIDDEN);
    }

    // 2) prep: RoPE+scale+split (q,k), transpose+split (v)
    {
        int total = NTOK * 40 * 64;
        prep_qk_kernel<<<(total + 255) / 256, 256>>>();
        dim3 grid(SS/32, D/32, BB*HK);
        prep_v_kernel<<<grid, dim3(32, 8)>>>();
    }

    // 3) tensor-core flash attention
    {
        dim3 grid(SS / 64, H, BB);
        flash_tc_kernel<<<grid, 128, FLASH2_SMEM>>>();
    }

    // 4) output projection
    {
        dim3 grid(HIDDEN / 128, NTOK / 128);
        tf32_gemm_kernel<<<grid, 128>>>(attn_ptr, w_o, out, NTOK, HIDDEN, H*D);
    }
}